// round 16
// baseline (speedup 1.0000x reference)
#include <cuda_runtime.h>
#include <cuda_fp16.h>
#include <math.h>
#include <stdint.h>

// Problem dims (fixed by setup_inputs)
#define B_    4
#define L_    4096
#define D_    1024
#define HID_  128
#define NS_   1024
#define M_    16384
#define NCH_  16
#define TCH_  256
#define PI_F  3.14159265358979323846f

// ---------------- scratch (device globals; no allocations allowed) ----------
__device__ unsigned short g_X16  [(size_t)M_ * D_];    // X fp16 (32MB, r-path)
__device__ unsigned short g_W1r16[HID_ * D_];          // Wr1^T [n=128][k=1024] fp16
__device__ unsigned short g_W2r16[NS_ * HID_];         // Wr2^T [n=1024][k=128] fp16
__device__ float          g_Hbuf [(size_t)M_ * 256];   // fp32 H (m-half cols 128..255 used)
__device__ unsigned short g_Hr16 [(size_t)M_ * HID_];  // gelu hidden r fp16 (4MB)
__device__ float          g_am   [(size_t)M_ * NS_];   // raw accm (64MB)
__device__ float          g_alpha[(size_t)M_ * NS_];   // 64 MB
__device__ float          g_u    [(size_t)M_ * NS_];   // 64 MB
__device__ float          g_cA   [B_ * NS_ * NCH_];
__device__ float          g_cU   [B_ * NS_ * NCH_];
__device__ float          g_carry[B_ * NS_ * NCH_];

// ======================= helpers =======================
__device__ __forceinline__ uint32_t smem_u32(const void* p) {
    uint32_t a;
    asm("{ .reg .u64 t; cvta.to.shared.u64 t, %1; cvt.u32.u64 %0, t; }"
        : "=r"(a) : "l"(p));
    return a;
}
__device__ __forceinline__ void ldsm_x4(uint32_t* r, uint32_t addr) {
    asm volatile("ldmatrix.sync.aligned.m8n8.x4.shared.b16 {%0,%1,%2,%3}, [%4];"
        : "=r"(r[0]), "=r"(r[1]), "=r"(r[2]), "=r"(r[3]) : "r"(addr));
}
__device__ __forceinline__ void mma_f16(float* d, const uint32_t* a, const uint32_t* b) {
    asm volatile("mma.sync.aligned.m16n8k16.row.col.f32.f16.f16.f32 "
        "{%0,%1,%2,%3}, {%4,%5,%6,%7}, {%8,%9}, {%0,%1,%2,%3};"
        : "+f"(d[0]), "+f"(d[1]), "+f"(d[2]), "+f"(d[3])
        : "r"(a[0]), "r"(a[1]), "r"(a[2]), "r"(a[3]), "r"(b[0]), "r"(b[1]));
}
__device__ __forceinline__ float gelu_exact(float v) {
    return 0.5f * v * (1.0f + erff(v * 0.70710678118654752440f));
}
__device__ __forceinline__ unsigned short f16_of(float f) {
    __half h = __float2half_rn(f);
    return *reinterpret_cast<unsigned short*>(&h);
}

// ============================================================================
// Conversion kernels (r-path inputs to fp16)
// ============================================================================
__global__ __launch_bounds__(256) void k_convX(const float* __restrict__ X) {
    size_t i = ((size_t)blockIdx.x * 256 + threadIdx.x) * 4;
    float4 v = *reinterpret_cast<const float4*>(X + i);
    ushort4 h;
    h.x = f16_of(v.x); h.y = f16_of(v.y); h.z = f16_of(v.z); h.w = f16_of(v.w);
    *reinterpret_cast<ushort4*>(g_X16 + i) = h;
}
__global__ __launch_bounds__(256) void k_convW1r(const float* __restrict__ Wr1) {
    int id = blockIdx.x * 256 + threadIdx.x;    // 0..131071
    int n = id >> 10, k = id & 1023;
    g_W1r16[id] = f16_of(Wr1[k * HID_ + n]);
}
__global__ __launch_bounds__(256) void k_convW2r(const float* __restrict__ Wr2) {
    int id = blockIdx.x * 256 + threadIdx.x;    // 0..131071
    int n = id >> 7, k = id & 127;
    g_W2r16[id] = f16_of(Wr2[k * NS_ + n]);
}

// ============================================================================
// m-head GEMM1 (fp32, BIT-IDENTICAL to the R0 passing kernel, m-half only):
// H[:,128:256] = gelu(X @ Wm1 + bm1). grid (2,128); bn0 in {128,192}.
// ============================================================================
__global__ __launch_bounds__(256) void k_gemm1_m(
    const float* __restrict__ X,
    const float* __restrict__ Wm1, const float* __restrict__ bm1)
{
    const int bn0 = 128 + blockIdx.x * 64;     // 128 or 192
    const int bm0 = blockIdx.y * 128;
    const float* W    = Wm1;
    const float* bias = bm1;
    const int wcol0 = bn0 & 127;

    __shared__ float As[16][128];
    __shared__ float Bs[16][64];

    const int tid = threadIdx.x;
    const int tx = tid & 15;
    const int ty = tid >> 4;

    float acc[8][4];
    #pragma unroll
    for (int i = 0; i < 8; i++)
        #pragma unroll
        for (int j = 0; j < 4; j++) acc[i][j] = 0.f;

    for (int k0 = 0; k0 < D_; k0 += 16) {
        #pragma unroll
        for (int i = 0; i < 2; i++) {
            int f   = tid + i * 256;
            int row = f >> 2;
            int c4  = (f & 3) * 4;
            float4 v = *reinterpret_cast<const float4*>(
                &X[(size_t)(bm0 + row) * D_ + k0 + c4]);
            As[c4 + 0][row] = v.x; As[c4 + 1][row] = v.y;
            As[c4 + 2][row] = v.z; As[c4 + 3][row] = v.w;
        }
        {
            int row = tid >> 4;
            int c4  = (tid & 15) * 4;
            float4 v = *reinterpret_cast<const float4*>(
                &W[(size_t)(k0 + row) * HID_ + wcol0 + c4]);
            *reinterpret_cast<float4*>(&Bs[row][c4]) = v;
        }
        __syncthreads();
        #pragma unroll
        for (int k = 0; k < 16; k++) {
            float a[8], b[4];
            float4 a0 = *reinterpret_cast<const float4*>(&As[k][ty * 8]);
            float4 a1 = *reinterpret_cast<const float4*>(&As[k][ty * 8 + 4]);
            a[0]=a0.x; a[1]=a0.y; a[2]=a0.z; a[3]=a0.w;
            a[4]=a1.x; a[5]=a1.y; a[6]=a1.z; a[7]=a1.w;
            float4 bb = *reinterpret_cast<const float4*>(&Bs[k][tx * 4]);
            b[0]=bb.x; b[1]=bb.y; b[2]=bb.z; b[3]=bb.w;
            #pragma unroll
            for (int i = 0; i < 8; i++)
                #pragma unroll
                for (int j = 0; j < 4; j++)
                    acc[i][j] = fmaf(a[i], b[j], acc[i][j]);
        }
        __syncthreads();
    }

    #pragma unroll
    for (int j = 0; j < 4; j++) {
        float bj = bias[wcol0 + tx * 4 + j];
        #pragma unroll
        for (int i = 0; i < 8; i++) {
            int m = bm0 + ty * 8 + i;
            float v = acc[i][j] + bj;
            g_Hbuf[(size_t)m * 256 + bn0 + tx * 4 + j] = gelu_exact(v);
        }
    }
}

// ============================================================================
// m-head GEMM2 (fp32, accm chain BIT-IDENTICAL to R0): writes raw accm to g_am.
// BM=64, BN=64, BK=32, grid (16,256).
// ============================================================================
__global__ __launch_bounds__(256) void k_gemm2_m(const float* __restrict__ Wm2)
{
    const int n0 = blockIdx.x * 64;
    const int m0 = blockIdx.y * 64;

    __shared__ float Ams[32][64];
    __shared__ float Bms[32][64];

    const int tid = threadIdx.x;
    const int tx = tid & 15;
    const int ty = tid >> 4;

    float accm[4][4];
    #pragma unroll
    for (int i = 0; i < 4; i++)
        #pragma unroll
        for (int j = 0; j < 4; j++) accm[i][j] = 0.f;

    for (int k0 = 0; k0 < HID_; k0 += 32) {
        #pragma unroll
        for (int i = 0; i < 2; i++) {
            int f   = tid + i * 256;
            int row = f >> 3;
            int c4  = (f & 7) * 4;
            const float* src = &g_Hbuf[(size_t)(m0 + row) * 256 + k0 + c4];
            float4 vm = *reinterpret_cast<const float4*>(src + 128);
            Ams[c4+0][row]=vm.x; Ams[c4+1][row]=vm.y; Ams[c4+2][row]=vm.z; Ams[c4+3][row]=vm.w;
        }
        #pragma unroll
        for (int i = 0; i < 2; i++) {
            int f   = tid + i * 256;
            int row = f >> 4;
            int c4  = (f & 15) * 4;
            float4 vm = *reinterpret_cast<const float4*>(
                &Wm2[(size_t)(k0 + row) * NS_ + n0 + c4]);
            *reinterpret_cast<float4*>(&Bms[row][c4]) = vm;
        }
        __syncthreads();
        #pragma unroll
        for (int k = 0; k < 32; k++) {
            float4 am = *reinterpret_cast<const float4*>(&Ams[k][ty * 4]);
            float4 bm = *reinterpret_cast<const float4*>(&Bms[k][tx * 4]);
            float amr[4] = {am.x, am.y, am.z, am.w};
            float bmr[4] = {bm.x, bm.y, bm.z, bm.w};
            #pragma unroll
            for (int i = 0; i < 4; i++)
                #pragma unroll
                for (int j = 0; j < 4; j++)
                    accm[i][j] = fmaf(amr[i], bmr[j], accm[i][j]);
        }
        __syncthreads();
    }

    #pragma unroll
    for (int j = 0; j < 4; j++) {
        int c = n0 + tx * 4 + j;
        #pragma unroll
        for (int i = 0; i < 4; i++) {
            int m = m0 + ty * 4 + i;
            g_am[(size_t)m * NS_ + c] = accm[i][j];
        }
    }
}

// ============================================================================
// r-head GEMM1 (TC fp16): H_r = gelu(X @ Wr1 + br1). M=16384, N=128, K=1024.
// CTA 128m x 128n, 8 warps (4m x 2n), BK=32.
// ============================================================================
__global__ __launch_bounds__(256, 1) void k_gemm1_r(const float* __restrict__ br1)
{
    __shared__ __align__(16) unsigned short Ah[128 * 40];
    __shared__ __align__(16) unsigned short Bh[128 * 40];
    __shared__ float bias_s[128];

    const int tid = threadIdx.x;
    const int lane = tid & 31, wid = tid >> 5;
    const int wm = wid & 3, wn = wid >> 2;
    const int m0 = blockIdx.x * 128;

    if (tid < 128) bias_s[tid] = br1[tid];

    float acc[2][8][4];
    #pragma unroll
    for (int i = 0; i < 2; i++)
        #pragma unroll
        for (int j = 0; j < 8; j++)
            #pragma unroll
            for (int q = 0; q < 4; q++) acc[i][j][q] = 0.f;

    const uint32_t sAh = smem_u32(Ah), sBh = smem_u32(Bh);

    const int a_row   = wm * 32 + (lane & 15);
    const int a_cbase = (lane >> 4) * 8;
    const int b_nrow  = wn * 64 + ((lane >> 4) * 8) + (lane & 7);
    const int b_koff  = ((lane >> 3) & 1) * 8;

    for (int k0 = 0; k0 < D_; k0 += 32) {
        #pragma unroll
        for (int i = 0; i < 2; i++) {
            int id = tid + i * 256;
            int row = id >> 2, c = (id & 3) * 8;
            *reinterpret_cast<uint4*>(&Ah[row * 40 + c]) =
                *reinterpret_cast<const uint4*>(&g_X16[(size_t)(m0 + row) * D_ + k0 + c]);
            *reinterpret_cast<uint4*>(&Bh[row * 40 + c]) =
                *reinterpret_cast<const uint4*>(&g_W1r16[(size_t)row * D_ + k0 + c]);
        }
        __syncthreads();
        #pragma unroll
        for (int ks = 0; ks < 2; ks++) {
            uint32_t af[2][4];
            #pragma unroll
            for (int mf = 0; mf < 2; mf++)
                ldsm_x4(af[mf], sAh + (uint32_t)(((a_row + mf * 16) * 40 + ks * 16 + a_cbase) * 2));
            uint32_t bf[8][2];
            #pragma unroll
            for (int p = 0; p < 4; p++) {
                uint32_t t[4];
                ldsm_x4(t, sBh + (uint32_t)(((b_nrow + p * 16) * 40 + ks * 16 + b_koff) * 2));
                bf[2*p][0] = t[0]; bf[2*p][1] = t[1];
                bf[2*p+1][0] = t[2]; bf[2*p+1][1] = t[3];
            }
            #pragma unroll
            for (int mf = 0; mf < 2; mf++)
                #pragma unroll
                for (int nf = 0; nf < 8; nf++)
                    mma_f16(acc[mf][nf], af[mf], bf[nf]);
        }
        __syncthreads();
    }

    // Epilogue: bias + exact GELU, store fp16
    #pragma unroll
    for (int mf = 0; mf < 2; mf++)
        #pragma unroll
        for (int nf = 0; nf < 8; nf++) {
            int cl = wn * 64 + nf * 8 + 2 * (lane & 3);
            float b0 = bias_s[cl], b1 = bias_s[cl + 1];
            #pragma unroll
            for (int hf = 0; hf < 2; hf++) {
                int m = m0 + wm * 32 + mf * 16 + (lane >> 2) + hf * 8;
                float g0 = gelu_exact(acc[mf][nf][hf * 2]     + b0);
                float g1 = gelu_exact(acc[mf][nf][hf * 2 + 1] + b1);
                *reinterpret_cast<uint32_t*>(&g_Hr16[(size_t)m * HID_ + cl]) =
                    (uint32_t)f16_of(g0) | ((uint32_t)f16_of(g1) << 16);
            }
        }
}

// ============================================================================
// r-head GEMM2 (TC fp16) + fused Kalman epilogue (z/nu math expression-identical
// to the R0 kernel, with am read from the bit-exact fp32 m-path).
// CTA 128m x 128n; K=128 (4 iters of BK=32).
// ============================================================================
__global__ __launch_bounds__(256, 1) void k_gemm2_r(
    const float* __restrict__ br2, const float* __restrict__ bm2,
    const float* __restrict__ theta, const float* __restrict__ log_Pi,
    float* __restrict__ outK, float* __restrict__ outR)
{
    __shared__ __align__(16) unsigned short Ah[128 * 40];
    __shared__ __align__(16) unsigned short Bh[128 * 40];
    __shared__ float brs[128], bms[128], Pis[128];

    const int tid = threadIdx.x;
    const int lane = tid & 31, wid = tid >> 5;
    const int wm = wid & 3, wn = wid >> 2;
    const int n0 = blockIdx.x * 128;
    const int m0 = blockIdx.y * 128;

    if (tid < 128) {
        brs[tid] = br2[n0 + tid];
        bms[tid] = bm2[n0 + tid];
        Pis[tid] = expf(log_Pi[n0 + tid]);
    }

    float acc[2][8][4];
    #pragma unroll
    for (int i = 0; i < 2; i++)
        #pragma unroll
        for (int j = 0; j < 8; j++)
            #pragma unroll
            for (int q = 0; q < 4; q++) acc[i][j][q] = 0.f;

    const uint32_t sAh = smem_u32(Ah), sBh = smem_u32(Bh);

    const int a_row   = wm * 32 + (lane & 15);
    const int a_cbase = (lane >> 4) * 8;
    const int b_nrow  = wn * 64 + ((lane >> 4) * 8) + (lane & 7);
    const int b_koff  = ((lane >> 3) & 1) * 8;

    __syncthreads();

    #pragma unroll
    for (int k0 = 0; k0 < HID_; k0 += 32) {
        #pragma unroll
        for (int i = 0; i < 2; i++) {
            int id = tid + i * 256;
            int row = id >> 2, c = (id & 3) * 8;
            *reinterpret_cast<uint4*>(&Ah[row * 40 + c]) =
                *reinterpret_cast<const uint4*>(&g_Hr16[(size_t)(m0 + row) * HID_ + k0 + c]);
            *reinterpret_cast<uint4*>(&Bh[row * 40 + c]) =
                *reinterpret_cast<const uint4*>(&g_W2r16[(size_t)(n0 + row) * HID_ + k0 + c]);
        }
        __syncthreads();
        #pragma unroll
        for (int ks = 0; ks < 2; ks++) {
            uint32_t af[2][4];
            #pragma unroll
            for (int mf = 0; mf < 2; mf++)
                ldsm_x4(af[mf], sAh + (uint32_t)(((a_row + mf * 16) * 40 + ks * 16 + a_cbase) * 2));
            uint32_t bf[8][2];
            #pragma unroll
            for (int p = 0; p < 4; p++) {
                uint32_t t[4];
                ldsm_x4(t, sBh + (uint32_t)(((b_nrow + p * 16) * 40 + ks * 16 + b_koff) * 2));
                bf[2*p][0] = t[0]; bf[2*p][1] = t[1];
                bf[2*p+1][0] = t[2]; bf[2*p+1][1] = t[3];
            }
            #pragma unroll
            for (int mf = 0; mf < 2; mf++)
                #pragma unroll
                for (int nf = 0; nf < 8; nf++)
                    mma_f16(acc[mf][nf], af[mf], bf[nf]);
        }
        __syncthreads();
    }

    // Fused Kalman epilogue
    #pragma unroll
    for (int mf = 0; mf < 2; mf++)
        #pragma unroll
        for (int nf = 0; nf < 8; nf++) {
            int cl = wn * 64 + nf * 8 + 2 * (lane & 3);
            float brA = brs[cl], brB = brs[cl + 1];
            float bmA = bms[cl], bmB = bms[cl + 1];
            float PiA = Pis[cl], PiB = Pis[cl + 1];
            #pragma unroll
            for (int hf = 0; hf < 2; hf++) {
                int m = m0 + wm * 32 + mf * 16 + (lane >> 2) + hf * 8;
                size_t idx = (size_t)m * NS_ + n0 + cl;
                float2 th = *reinterpret_cast<const float2*>(&theta[idx]);
                float2 amv = *reinterpret_cast<const float2*>(&g_am[idx]);

                float ar0 = acc[mf][nf][hf * 2]     + brA;
                float ar1 = acc[mf][nf][hf * 2 + 1] + brB;

                float R0 = expf(fminf(fmaxf(ar0, -5.0f), 5.0f));
                float R1 = expf(fminf(fmaxf(ar1, -5.0f), 5.0f));
                // z/nu path: identical expressions + bit-identical am as R0
                float z0 = PI_F * tanhf(amv.x + bmA);
                float z1 = PI_F * tanhf(amv.y + bmB);
                float d0 = z0 - th.x, d1 = z1 - th.y;
                float nu0 = atan2f(sinf(d0), cosf(d0));
                float nu1 = atan2f(sinf(d1), cosf(d1));
                float K0 = PiA / fmaxf(PiA + R0, 1e-8f);
                float K1 = PiB / fmaxf(PiB + R1, 1e-8f);

                *reinterpret_cast<float2*>(&outR[idx])    = make_float2(R0, R1);
                *reinterpret_cast<float2*>(&outK[idx])    = make_float2(K0, K1);
                *reinterpret_cast<float2*>(&g_alpha[idx]) = make_float2(1.0f - K0, 1.0f - K1);
                *reinterpret_cast<float2*>(&g_u[idx])     = make_float2(K0 * nu0, K1 * nu1);
            }
        }
}

// ============================================================================
// Scan pass 1: per (b, c, chunk) aggregate  A = prod(alpha), U = chunk-scan end
// ============================================================================
__global__ __launch_bounds__(256) void k_scan1()
{
    int g = blockIdx.x * blockDim.x + threadIdx.x;   // 0..65535
    int c     = g & (NS_ - 1);
    int rest  = g >> 10;
    int chunk = rest & (NCH_ - 1);
    int b     = rest >> 4;
    size_t base = ((size_t)(b * L_ + chunk * TCH_)) * NS_ + c;
    float A = 1.0f, U = 0.0f;
    #pragma unroll 8
    for (int j = 0; j < TCH_; j++) {
        float al = g_alpha[base + (size_t)j * NS_];
        float uu = g_u    [base + (size_t)j * NS_];
        A *= al;
        U = fmaf(al, U, uu);
    }
    int sidx = ((b * NS_ + c) * NCH_) + chunk;
    g_cA[sidx] = A;
    g_cU[sidx] = U;
}

// ============================================================================
// Scan pass 2: per channel, sequential scan over 16 chunk aggregates. + Pi out
// ============================================================================
__global__ __launch_bounds__(256) void k_scan2(const float* __restrict__ log_Pi,
                                               float* __restrict__ outPi)
{
    int ch = blockIdx.x * blockDim.x + threadIdx.x;  // 0..4095
    if (ch < NS_) outPi[ch] = expf(log_Pi[ch]);
    if (ch >= B_ * NS_) return;
    float d = 0.0f;
    int base = ch * NCH_;
    #pragma unroll
    for (int k = 0; k < NCH_; k++) {
        g_carry[base + k] = d;
        d = fmaf(g_cA[base + k], d, g_cU[base + k]);
    }
}

// ============================================================================
// Scan pass 3: re-scan each chunk with its carry, write theta_hat.
// ============================================================================
__global__ __launch_bounds__(256) void k_scan3(const float* __restrict__ theta,
                                               float* __restrict__ outTheta)
{
    int g = blockIdx.x * blockDim.x + threadIdx.x;
    int c     = g & (NS_ - 1);
    int rest  = g >> 10;
    int chunk = rest & (NCH_ - 1);
    int b     = rest >> 4;
    size_t base = ((size_t)(b * L_ + chunk * TCH_)) * NS_ + c;
    float d = g_carry[((b * NS_ + c) * NCH_) + chunk];
    #pragma unroll 8
    for (int j = 0; j < TCH_; j++) {
        size_t idx = base + (size_t)j * NS_;
        float al = g_alpha[idx];
        float uu = g_u[idx];
        d = fmaf(al, d, uu);
        outTheta[idx] = theta[idx] + d;
    }
}

// ============================================================================
// Launch
// Inputs (metadata order): theta_path, content_emb, log_Pi,
//                          Wr1, br1, Wr2, br2, Wm1, bm1, Wm2, bm2
// Output: [theta_hat (16777216), Pi (1024), K (16777216), R (16777216)]
// ============================================================================
extern "C" void kernel_launch(void* const* d_in, const int* in_sizes, int n_in,
                              void* d_out, int out_size)
{
    const float* theta  = (const float*)d_in[0];
    const float* x      = (const float*)d_in[1];
    const float* log_Pi = (const float*)d_in[2];
    const float* Wr1    = (const float*)d_in[3];
    const float* br1    = (const float*)d_in[4];
    const float* Wr2    = (const float*)d_in[5];
    const float* br2    = (const float*)d_in[6];
    const float* Wm1    = (const float*)d_in[7];
    const float* bm1    = (const float*)d_in[8];
    const float* Wm2    = (const float*)d_in[9];
    const float* bm2    = (const float*)d_in[10];

    float* outTheta = (float*)d_out;
    float* outPi    = outTheta + (size_t)M_ * NS_;
    float* outK     = outPi + NS_;
    float* outR     = outK + (size_t)M_ * NS_;

    // r-path fp16 conversions
    k_convX  <<<(int)(((size_t)M_ * D_) / 4 / 256), 256>>>(x);
    k_convW1r<<<(HID_ * D_) / 256, 256>>>(Wr1);
    k_convW2r<<<(NS_ * HID_) / 256, 256>>>(Wr2);

    // m-path (fp32, bit-identical to R0)
    dim3 g1m(2, 128);
    k_gemm1_m<<<g1m, 256>>>(x, Wm1, bm1);
    dim3 g2m(16, 256);
    k_gemm2_m<<<g2m, 256>>>(Wm2);

    // r-path (tensor cores)
    k_gemm1_r<<<128, 256>>>(br1);
    dim3 g2r(8, 128);
    k_gemm2_r<<<g2r, 256>>>(br2, bm2, theta, log_Pi, outK, outR);

    // Scan
    k_scan1<<<(B_ * NS_ * NCH_) / 256, 256>>>();
    k_scan2<<<(B_ * NS_ + 255) / 256, 256>>>(log_Pi, outPi);
    k_scan3<<<(B_ * NS_ * NCH_) / 256, 256>>>(theta, outTheta);
}